// round 5
// baseline (speedup 1.0000x reference)
#include <cuda_runtime.h>
#include <cuda_bf16.h>
#include <cstdint>

#define T_TOK 8192
#define DIM   1024
#define HID   2048
#define NE    8
#define RCAP  (T_TOK*2 + NE*128)   // 17408

// ---- GEMM2 (bf16x3) tiling ----
#define BM2 128
#define BN2 128
#define BK2 32
#define ROWB   80
#define TILEB  (128*ROWB)
#define STAGEB (4*TILEB)
#define SMEM2SZ (2*STAGEB)          // 81920

// ---- GEMM1 (int8 dual) tiling ----
#define BM1 64
#define BN1 128
#define BK1 64
#define ATILE (64*ROWB)             // 5120
#define BTILE (128*ROWB)            // 10240
#define STG1  (2*ATILE + 2*BTILE)   // 30720
#define SMEM1SZ (2*STG1)            // 61440

// ---------------- device scratch ----------------
__device__ int   g_cnt[NE], g_cur[NE], g_off[NE + 1];
__device__ int   g_tope[T_TOK * 2];
__device__ float g_topp[T_TOK * 2];
__device__ int   g_rowtok[RCAP];
__device__ float g_roww[RCAP];
__device__ float g_xs[RCAP];                         // per-row X scale (s/8192)
__device__ float g_ws[(size_t)NE * 2 * HID];         // per-col Wc scale (t/8192)
__device__ char  g_Xq_hi[(size_t)RCAP * DIM];
__device__ char  g_Xq_lo[(size_t)RCAP * DIM];
__device__ char  g_Wq_hi[(size_t)NE * 2 * HID * DIM];  // [e][2h+p][d]
__device__ char  g_Wq_lo[(size_t)NE * 2 * HID * DIM];
__device__ __nv_bfloat16 g_Sh[(size_t)RCAP * HID];
__device__ __nv_bfloat16 g_Sl[(size_t)RCAP * HID];
__device__ __nv_bfloat16 g_W3h[(size_t)NE * DIM * HID];  // [e][d][h]
__device__ __nv_bfloat16 g_W3l[(size_t)NE * DIM * HID];

// ---------------- helpers ----------------
__device__ __forceinline__ uint32_t smem_u32(const void* p) {
    uint32_t a;
    asm("{ .reg .u64 t; cvta.to.shared.u64 t, %1; cvt.u32.u64 %0, t; }" : "=r"(a) : "l"(p));
    return a;
}
__device__ __forceinline__ void cp16(uint32_t dst, const void* src) {
    asm volatile("cp.async.cg.shared.global [%0], [%1], 16;" :: "r"(dst), "l"(src));
}
#define CP_COMMIT() asm volatile("cp.async.commit_group;" ::: "memory")
#define CP_WAIT1()  asm volatile("cp.async.wait_group 1;" ::: "memory")
#define CP_WAIT0()  asm volatile("cp.async.wait_group 0;" ::: "memory")

__device__ __forceinline__ void ldsm4(uint32_t* r, uint32_t addr) {
    asm volatile("ldmatrix.sync.aligned.m8n8.x4.shared.b16 {%0,%1,%2,%3}, [%4];"
                 : "=r"(r[0]), "=r"(r[1]), "=r"(r[2]), "=r"(r[3]) : "r"(addr));
}
__device__ __forceinline__ void mma_bf16(float* c, const uint32_t* a, uint32_t b0, uint32_t b1) {
    asm volatile("mma.sync.aligned.m16n8k16.row.col.f32.bf16.bf16.f32 "
                 "{%0,%1,%2,%3}, {%4,%5,%6,%7}, {%8,%9}, {%0,%1,%2,%3};"
                 : "+f"(c[0]), "+f"(c[1]), "+f"(c[2]), "+f"(c[3])
                 : "r"(a[0]), "r"(a[1]), "r"(a[2]), "r"(a[3]), "r"(b0), "r"(b1));
}
__device__ __forceinline__ void mma_s8(int* c, const uint32_t* a, uint32_t b0, uint32_t b1) {
    asm volatile("mma.sync.aligned.m16n8k32.row.col.s32.s8.s8.s32 "
                 "{%0,%1,%2,%3}, {%4,%5,%6,%7}, {%8,%9}, {%0,%1,%2,%3};"
                 : "+r"(c[0]), "+r"(c[1]), "+r"(c[2]), "+r"(c[3])
                 : "r"(a[0]), "r"(a[1]), "r"(a[2]), "r"(a[3]), "r"(b0), "r"(b1));
}
__device__ __forceinline__ float swishf(float a) { return a / (1.0f + __expf(-a)); }
__device__ __forceinline__ void bsplit(float v, __nv_bfloat16& h, __nv_bfloat16& l) {
    h = __float2bfloat16(v);
    l = __float2bfloat16(v - __bfloat162float(h));
}
__device__ __forceinline__ void q14(float v, float inv, char& hi, char& lo) {
    int q = __float2int_rn(v * inv);
    q = max(-8191, min(8191, q));
    int h = (q + 64) >> 7;
    hi = (char)h;
    lo = (char)(q - (h << 7));
}

// ---------------- routing kernels ----------------
__global__ void k_init() {
    int i = blockIdx.x * blockDim.x + threadIdx.x;
    if (i < NE) { g_cnt[i] = 0; g_cur[i] = 0; }
    if (i < RCAP) g_rowtok[i] = -1;
}

__global__ void k_gate(const float* __restrict__ x, const float* __restrict__ Wg) {
    __shared__ float sWgT[NE * DIM];
    for (int idx = threadIdx.x; idx < DIM * NE; idx += blockDim.x) {
        int d = idx >> 3, e = idx & 7;
        sWgT[e * DIM + d] = Wg[idx];
    }
    __syncthreads();
    int warp = threadIdx.x >> 5, lane = threadIdx.x & 31;
    int t = blockIdx.x * 8 + warp;
    const float* xr = x + (size_t)t * DIM;
    float acc[NE];
#pragma unroll
    for (int e = 0; e < NE; e++) acc[e] = 0.0f;
    for (int d = lane; d < DIM; d += 32) {
        float xv = xr[d];
#pragma unroll
        for (int e = 0; e < NE; e++) acc[e] += xv * sWgT[e * DIM + d];
    }
#pragma unroll
    for (int off = 16; off; off >>= 1)
#pragma unroll
        for (int e = 0; e < NE; e++) acc[e] += __shfl_xor_sync(0xffffffffu, acc[e], off);
    if (lane == 0) {
        int e0 = 0; float v0 = acc[0];
#pragma unroll
        for (int e = 1; e < NE; e++) if (acc[e] > v0) { v0 = acc[e]; e0 = e; }
        int e1 = -1; float v1 = -1e30f;
#pragma unroll
        for (int e = 0; e < NE; e++) if (e != e0 && acc[e] > v1) { v1 = acc[e]; e1 = e; }
        float ex = __expf(v1 - v0);
        g_tope[t * 2 + 0] = e0; g_topp[t * 2 + 0] = 1.0f / (1.0f + ex);
        g_tope[t * 2 + 1] = e1; g_topp[t * 2 + 1] = ex / (1.0f + ex);
        atomicAdd(&g_cnt[e0], 1);
        atomicAdd(&g_cnt[e1], 1);
    }
}

__global__ void k_offsets() {
    if (threadIdx.x == 0) {
        int o = 0;
#pragma unroll
        for (int e = 0; e < NE; e++) {
            g_off[e] = o;
            o += ((g_cnt[e] + 127) / 128) * 128;
        }
        g_off[NE] = o;
    }
}

__global__ void k_scatter() {
    int i = blockIdx.x * blockDim.x + threadIdx.x;
    if (i >= T_TOK * 2) return;
    int e = g_tope[i];
    int pos = g_off[e] + atomicAdd(&g_cur[e], 1);
    g_rowtok[pos] = i >> 1;
    g_roww[pos] = g_topp[i];
}

// gather + per-row max + int14 dual quantization
__global__ void k_gatherq(const float* __restrict__ x) {
    __shared__ float red[8];
    int r = blockIdx.x;
    int t = g_rowtok[r];
    int tid = threadIdx.x, wid = tid >> 5, lane = tid & 31;
    float4 v = make_float4(0.f, 0.f, 0.f, 0.f);
    if (t >= 0) v = ((const float4*)(x + (size_t)t * DIM))[tid];
    float m = fmaxf(fmaxf(fabsf(v.x), fabsf(v.y)), fmaxf(fabsf(v.z), fabsf(v.w)));
#pragma unroll
    for (int off = 16; off; off >>= 1) m = fmaxf(m, __shfl_xor_sync(0xffffffffu, m, off));
    if (lane == 0) red[wid] = m;
    __syncthreads();
    if (tid == 0) {
        float s = red[0];
#pragma unroll
        for (int i = 1; i < 8; i++) s = fmaxf(s, red[i]);
        if (s < 1e-30f) s = 1.0f;
        red[0] = s;
        g_xs[r] = s * (1.0f / 8192.0f);
    }
    __syncthreads();
    float inv = 8192.0f / red[0];
    char h[4], l[4];
    q14(v.x, inv, h[0], l[0]); q14(v.y, inv, h[1], l[1]);
    q14(v.z, inv, h[2], l[2]); q14(v.w, inv, h[3], l[3]);
    size_t off = (size_t)r * DIM + tid * 4;
    *(char4*)(g_Xq_hi + off) = make_char4(h[0], h[1], h[2], h[3]);
    *(char4*)(g_Xq_lo + off) = make_char4(l[0], l[1], l[2], l[3]);
}

// per-column |max| of W1/W2 -> g_ws (interleaved index 2h+p)
__global__ void k_wmax(const float* __restrict__ W, int p) {
    int e = blockIdx.y;
    int h = blockIdx.x * 256 + threadIdx.x;
    const float* base = W + (size_t)e * DIM * HID + h;
    float m = 0.f;
    for (int d = 0; d < DIM; d++) m = fmaxf(m, fabsf(base[(size_t)d * HID]));
    if (m < 1e-30f) m = 1.f;
    g_ws[(size_t)e * 2 * HID + 2 * h + p] = m * (1.0f / 8192.0f);
}

// W1/W2 [e][d][h] -> quantized int8 hi/lo at [e][2h+p][d]
__global__ void k_tr12q(const float* __restrict__ src, int p) {
    __shared__ float t[32][33];
    int e = blockIdx.z;
    const float* s = src + (size_t)e * DIM * HID;
    int h0 = blockIdx.x * 32, d0 = blockIdx.y * 32;
    int tx = threadIdx.x, ty = threadIdx.y;
#pragma unroll
    for (int i = ty; i < 32; i += 8)
        t[i][tx] = s[(size_t)(d0 + i) * HID + h0 + tx];
    __syncthreads();
#pragma unroll
    for (int i = ty; i < 32; i += 8) {
        float v = t[tx][i];
        int n = 2 * (h0 + i) + p;
        float inv = 1.0f / g_ws[(size_t)e * 2 * HID + n];
        char h, l;
        q14(v, inv, h, l);
        size_t off = ((size_t)e * 2 * HID + n) * DIM + d0 + tx;
        g_Wq_hi[off] = h; g_Wq_lo[off] = l;
    }
}

// W3 [e][h][d] -> bf16 h/l at [e][d][h]
__global__ void k_tr3(const float* __restrict__ src) {
    __shared__ float t[32][33];
    int e = blockIdx.z;
    const float* s = src + (size_t)e * HID * DIM;
    int d0 = blockIdx.x * 32, h0 = blockIdx.y * 32;
    int tx = threadIdx.x, ty = threadIdx.y;
#pragma unroll
    for (int i = ty; i < 32; i += 8)
        t[i][tx] = s[(size_t)(h0 + i) * DIM + d0 + tx];
    __syncthreads();
#pragma unroll
    for (int i = ty; i < 32; i += 8) {
        float v = t[tx][i];
        __nv_bfloat16 h, l; bsplit(v, h, l);
        size_t off = ((size_t)e * DIM + d0 + i) * HID + h0 + tx;
        g_W3h[off] = h; g_W3l[off] = l;
    }
}

// ---------------- GEMM1: int8 dual IMMA, epilogue SwiGLU -> Sh/Sl ----------------
__device__ __forceinline__ void load_stage1(
    uint32_t st, int tid, int k0,
    const char* Ah, const char* Al, const char* Bh, const char* Bl)
{
    {   // A: 64 rows x 64B, 1 cp per array per thread
        int row = tid >> 2, kc = tid & 3;
        uint32_t doff = row * ROWB + kc * 16;
        size_t goff = (size_t)row * DIM + k0 + kc * 16;
        cp16(st + doff,         Ah + goff);
        cp16(st + ATILE + doff, Al + goff);
    }
#pragma unroll
    for (int rep = 0; rep < 2; rep++) {  // B: 128 rows x 64B, 2 cps per array per thread
        int c = tid + rep * 256;
        int row = c >> 2, kc = c & 3;
        uint32_t doff = 2 * ATILE + row * ROWB + kc * 16;
        size_t goff = (size_t)row * DIM + k0 + kc * 16;
        cp16(st + doff,         Bh + goff);
        cp16(st + BTILE + doff, Bl + goff);
    }
    CP_COMMIT();
}

__device__ __forceinline__ void compute_stage1(
    uint32_t st, int warpM, int warpN, int lane,
    int hh[2][4][4], int cr[2][4][4])
{
    int mlane = lane & 7;
    int mid = lane >> 3;
#pragma unroll
    for (int ks = 0; ks < 2; ks++) {
        uint32_t ah[2][4], al[2][4];
#pragma unroll
        for (int mi = 0; mi < 2; mi++) {
            int row = warpM * 32 + mi * 16 + ((mid & 1) << 3) + mlane;
            int colB = ks * 32 + ((mid >> 1) << 4);
            ldsm4(ah[mi], st + row * ROWB + colB);
            ldsm4(al[mi], st + ATILE + row * ROWB + colB);
        }
#pragma unroll
        for (int njp = 0; njp < 2; njp++) {
            uint32_t bh[4], bl[4];
            int row = warpN * 32 + njp * 16 + ((mid >> 1) << 3) + mlane;
            int colB = ks * 32 + ((mid & 1) << 4);
            ldsm4(bh, st + 2 * ATILE + row * ROWB + colB);
            ldsm4(bl, st + 2 * ATILE + BTILE + row * ROWB + colB);
#pragma unroll
            for (int mi = 0; mi < 2; mi++)
#pragma unroll
                for (int j = 0; j < 2; j++) {
                    int nt = njp * 2 + j;
                    mma_s8(hh[mi][nt], ah[mi], bh[j * 2], bh[j * 2 + 1]);
                    mma_s8(cr[mi][nt], ah[mi], bl[j * 2], bl[j * 2 + 1]);
                    mma_s8(cr[mi][nt], al[mi], bh[j * 2], bh[j * 2 + 1]);
                }
        }
    }
}

__global__ __launch_bounds__(256, 2) void k_gemm1i8() {
    int row0 = blockIdx.y * BM1;
    int e = 0;
#pragma unroll
    for (int i = 1; i < NE; i++) if (g_off[i] <= row0) e = i;
    if (g_cnt[e] - (row0 - g_off[e]) <= 0) return;

    extern __shared__ __align__(128) char smem[];
    uint32_t sb = smem_u32(smem);
    int tid = threadIdx.x, wid = tid >> 5, lane = tid & 31;
    int warpM = wid >> 2, warpN = wid & 3;
    int n0 = blockIdx.x * BN1;

    const char* Ah = g_Xq_hi + (size_t)row0 * DIM;
    const char* Al = g_Xq_lo + (size_t)row0 * DIM;
    const char* Bh = g_Wq_hi + ((size_t)e * 2 * HID + n0) * DIM;
    const char* Bl = g_Wq_lo + ((size_t)e * 2 * HID + n0) * DIM;

    int hh[2][4][4], cr[2][4][4];
#pragma unroll
    for (int a = 0; a < 2; a++)
#pragma unroll
        for (int b = 0; b < 4; b++)
#pragma unroll
            for (int c = 0; c < 4; c++) { hh[a][b][c] = 0; cr[a][b][c] = 0; }

    const int NC = DIM / BK1;   // 16
    load_stage1(sb, tid, 0, Ah, Al, Bh, Bl);
    load_stage1(sb + STG1, tid, BK1, Ah, Al, Bh, Bl);
    for (int c = 0; c < NC; c++) {
        if (c == NC - 1) { CP_WAIT0(); } else { CP_WAIT1(); }
        __syncthreads();
        compute_stage1(sb + (c & 1) * STG1, warpM, warpN, lane, hh, cr);
        __syncthreads();
        if (c + 2 < NC)
            load_stage1(sb + (c & 1) * STG1, tid, (c + 2) * BK1, Ah, Al, Bh, Bl);
    }

    // epilogue: rescale int32 -> fp32, SwiGLU pair, bsplit -> Sh/Sl
    int qrow = lane >> 2, qcol = lane & 3;
#pragma unroll
    for (int mi = 0; mi < 2; mi++) {
        int r0 = row0 + warpM * 32 + mi * 16 + qrow;
        float xs0 = g_xs[r0], xs1 = g_xs[r0 + 8];
#pragma unroll
        for (int nt = 0; nt < 4; nt++) {
            int n = n0 + warpN * 32 + nt * 8 + qcol * 2;
            float t0 = g_ws[(size_t)e * 2 * HID + n];
            float t1 = g_ws[(size_t)e * 2 * HID + n + 1];
            float a1 = xs0 * t0 * (__int2float_rn(hh[mi][nt][0]) * 16384.f +
                                   __int2float_rn(cr[mi][nt][0]) * 128.f);
            float a2 = xs0 * t1 * (__int2float_rn(hh[mi][nt][1]) * 16384.f +
                                   __int2float_rn(cr[mi][nt][1]) * 128.f);
            float b1 = xs1 * t0 * (__int2float_rn(hh[mi][nt][2]) * 16384.f +
                                   __int2float_rn(cr[mi][nt][2]) * 128.f);
            float b2 = xs1 * t1 * (__int2float_rn(hh[mi][nt][3]) * 16384.f +
                                   __int2float_rn(cr[mi][nt][3]) * 128.f);
            int jg = n >> 1;
            __nv_bfloat16 h, l;
            bsplit(swishf(a1) * a2, h, l);
            g_Sh[(size_t)r0 * HID + jg] = h;       g_Sl[(size_t)r0 * HID + jg] = l;
            bsplit(swishf(b1) * b2, h, l);
            g_Sh[(size_t)(r0 + 8) * HID + jg] = h; g_Sl[(size_t)(r0 + 8) * HID + jg] = l;
        }
    }
}

// ---------------- GEMM2: bf16x3, out[t] += w * (S @ W3T) ----------------
__device__ __forceinline__ void load_stage2(
    uint32_t st, int tid, int k0,
    const __nv_bfloat16* Ah, const __nv_bfloat16* Al,
    const __nv_bfloat16* Bh, const __nv_bfloat16* Bl)
{
#pragma unroll
    for (int rep = 0; rep < 2; rep++) {
        int c = tid + rep * 256;
        int row = c >> 2, kc = c & 3;
        uint32_t doff = row * ROWB + kc * 16;
        size_t goff = (size_t)row * HID + k0 + kc * 8;
        cp16(st + doff,             Ah + goff);
        cp16(st + TILEB + doff,     Al + goff);
        cp16(st + 2 * TILEB + doff, Bh + goff);
        cp16(st + 3 * TILEB + doff, Bl + goff);
    }
    CP_COMMIT();
}

__device__ __forceinline__ void compute_stage2(
    uint32_t st, int warpM, int warpN, int lane, float acc[2][8][4])
{
    int mlane = lane & 7;
    int mid = lane >> 3;
#pragma unroll
    for (int ks = 0; ks < 2; ks++) {
        uint32_t ah[2][4], al[2][4];
#pragma unroll
        for (int mi = 0; mi < 2; mi++) {
            int row = warpM * 32 + mi * 16 + ((mid & 1) << 3) + mlane;
            int colB = ks * 32 + ((mid >> 1) << 4);
            ldsm4(ah[mi], st + row * ROWB + colB);
            ldsm4(al[mi], st + TILEB + row * ROWB + colB);
        }
#pragma unroll
        for (int njp = 0; njp < 2; njp++) {
            uint32_t bh[2][4], bl[2][4];
#pragma unroll
            for (int jj = 0; jj < 2; jj++) {
                int nj = njp * 2 + jj;
                int row = warpN * 64 + nj * 16 + ((mid >> 1) << 3) + mlane;
                int colB = ks * 32 + ((mid & 1) << 4);
                ldsm4(bh[jj], st + 2 * TILEB + row * ROWB + colB);
                ldsm4(bl[jj], st + 3 * TILEB + row * ROWB + colB);
            }
#pragma unroll
            for (int mi = 0; mi < 2; mi++)
#pragma unroll
                for (int jj = 0; jj < 2; jj++)
#pragma unroll
                    for (int tt = 0; tt < 2; tt++) {
                        int ni = (njp * 2 + jj) * 2 + tt;
                        mma_bf16(acc[mi][ni], ah[mi], bh[jj][tt * 2], bh[jj][tt * 2 + 1]);
                        mma_bf16(acc[mi][ni], ah[mi], bl[jj][tt * 2], bl[jj][tt * 2 + 1]);
                        mma_bf16(acc[mi][ni], al[mi], bh[jj][tt * 2], bh[jj][tt * 2 + 1]);
                    }
        }
    }
}

__global__ __launch_bounds__(256, 2) void k_gemm2(float* __restrict__ out) {
    int row0 = blockIdx.y * BM2;
    int e = 0;
#pragma unroll
    for (int i = 1; i < NE; i++) if (g_off[i] <= row0) e = i;
    if (g_cnt[e] - (row0 - g_off[e]) <= 0) return;

    extern __shared__ __align__(128) char smem[];
    uint32_t sb = smem_u32(smem);
    int tid = threadIdx.x, wid = tid >> 5, lane = tid & 31;
    int warpM = wid >> 1, warpN = wid & 1;
    int n0 = blockIdx.x * BN2;

    const __nv_bfloat16* Ah = g_Sh + (size_t)row0 * HID;
    const __nv_bfloat16* Al = g_Sl + (size_t)row0 * HID;
    const __nv_bfloat16* Bh = g_W3h + (size_t)e * DIM * HID + (size_t)n0 * HID;
    const __nv_bfloat16* Bl = g_W3l + (size_t)e * DIM * HID + (size_t)n0 * HID;

    float acc[2][8][4];
#pragma unroll
    for (int a = 0; a < 2; a++)
#pragma unroll
        for (int b = 0; b < 8; b++)
#pragma unroll
            for (int c = 0; c < 4; c++) acc[a][b][c] = 0.0f;

    const int NC = HID / BK2;   // 64
    load_stage2(sb, tid, 0, Ah, Al, Bh, Bl);
    load_stage2(sb + STAGEB, tid, BK2, Ah, Al, Bh, Bl);
    for (int c = 0; c < NC; c++) {
        if (c == NC - 1) { CP_WAIT0(); } else { CP_WAIT1(); }
        __syncthreads();
        compute_stage2(sb + (c & 1) * STAGEB, warpM, warpN, lane, acc);
        __syncthreads();
        if (c + 2 < NC)
            load_stage2(sb + (c & 1) * STAGEB, tid, (c + 2) * BK2, Ah, Al, Bh, Bl);
    }

    int qrow = lane >> 2, qcol = lane & 3;
#pragma unroll
    for (int mi = 0; mi < 2; mi++) {
        int rbase = row0 + warpM * 32 + mi * 16 + qrow;
#pragma unroll
        for (int half = 0; half < 2; half++) {
            int r = rbase + half * 8;
            int t = g_rowtok[r];
            if (t < 0) continue;
            float wgt = g_roww[r];
            float* orow = out + (size_t)t * DIM;
#pragma unroll
            for (int ni = 0; ni < 8; ni++) {
                int colg = blockIdx.x * BN2 + warpN * 64 + ni * 8 + qcol * 2;
                atomicAdd(orow + colg,     wgt * acc[mi][ni][half * 2]);
                atomicAdd(orow + colg + 1, wgt * acc[mi][ni][half * 2 + 1]);
            }
        }
    }
}

// ---------------- launch ----------------
extern "C" void kernel_launch(void* const* d_in, const int* in_sizes, int n_in,
                              void* d_out, int out_size) {
    const float* x  = (const float*)d_in[0];
    const float* Wg = (const float*)d_in[1];
    const float* W1 = (const float*)d_in[2];
    const float* W2 = (const float*)d_in[3];
    const float* W3 = (const float*)d_in[4];
    float* out = (float*)d_out;

    cudaFuncSetAttribute(k_gemm1i8, cudaFuncAttributeMaxDynamicSharedMemorySize, SMEM1SZ);
    cudaFuncSetAttribute(k_gemm2,   cudaFuncAttributeMaxDynamicSharedMemorySize, SMEM2SZ);

    cudaMemsetAsync(out, 0, (size_t)T_TOK * DIM * sizeof(float));
    k_init<<<(RCAP + 255) / 256, 256>>>();
    k_gate<<<T_TOK / 8, 256>>>(x, Wg);
    k_offsets<<<1, 32>>>();
    k_scatter<<<(T_TOK * 2 + 255) / 256, 256>>>();
    k_gatherq<<<RCAP, 256>>>(x);
    k_wmax<<<dim3(HID / 256, NE), 256>>>(W1, 0);
    k_wmax<<<dim3(HID / 256, NE), 256>>>(W2, 1);
    k_tr12q<<<dim3(HID / 32, DIM / 32, NE), dim3(32, 8)>>>(W1, 0);
    k_tr12q<<<dim3(HID / 32, DIM / 32, NE), dim3(32, 8)>>>(W2, 1);
    k_tr3<<<dim3(DIM / 32, HID / 32, NE), dim3(32, 8)>>>(W3);

    k_gemm1i8<<<dim3(2 * HID / BN1, RCAP / BM1), 256, SMEM1SZ>>>();
    k_gemm2<<<dim3(DIM / BN2, RCAP / BM2), 256, SMEM2SZ>>>(out);
}

// round 6
// speedup vs baseline: 2.0697x; 2.0697x over previous
#include <cuda_runtime.h>
#include <cuda_bf16.h>
#include <cstdint>

#define T_TOK 8192
#define DIM   1024
#define HID   2048
#define NE    8
#define BM    128
#define BN    128
#define BK    32
#define RCAP  (T_TOK*2 + NE*128)   // 17408 rows = 136 tiles of 128

// smem tile: 128 rows x 32 bf16 (64B) padded to 80B rows (conflict-free ldmatrix)
#define ROWB   80
#define TILEB  (128*ROWB)          // 10240 B
#define STAGEB (4*TILEB)           // Ah, Al, Bh, Bl = 40960 B
#define SMEMSZ (2*STAGEB)          // 81920 B -> 2 CTAs/SM

// ---------------- device scratch ----------------
__device__ int   g_cnt[NE], g_cur[NE], g_off[NE + 1];
__device__ int   g_tope[T_TOK * 2];
__device__ float g_topp[T_TOK * 2];
__device__ int   g_rowtok[RCAP];
__device__ float g_roww[RCAP];
__device__ __nv_bfloat16 g_Xh[(size_t)RCAP * DIM];
__device__ __nv_bfloat16 g_Xl[(size_t)RCAP * DIM];
__device__ __nv_bfloat16 g_Sh[(size_t)RCAP * HID];
__device__ __nv_bfloat16 g_Sl[(size_t)RCAP * HID];
__device__ __nv_bfloat16 g_Wch[(size_t)NE * 2 * HID * DIM];  // [e][2h+p][d]
__device__ __nv_bfloat16 g_Wcl[(size_t)NE * 2 * HID * DIM];
__device__ __nv_bfloat16 g_W3h[(size_t)NE * DIM * HID];      // [e][d][h]
__device__ __nv_bfloat16 g_W3l[(size_t)NE * DIM * HID];

// ---------------- helpers ----------------
__device__ __forceinline__ uint32_t smem_u32(const void* p) {
    uint32_t a;
    asm("{ .reg .u64 t; cvta.to.shared.u64 t, %1; cvt.u32.u64 %0, t; }" : "=r"(a) : "l"(p));
    return a;
}
__device__ __forceinline__ void cp16(uint32_t dst, const void* src) {
    asm volatile("cp.async.cg.shared.global [%0], [%1], 16;" :: "r"(dst), "l"(src));
}
#define CP_COMMIT() asm volatile("cp.async.commit_group;" ::: "memory")
#define CP_WAIT1()  asm volatile("cp.async.wait_group 1;" ::: "memory")
#define CP_WAIT0()  asm volatile("cp.async.wait_group 0;" ::: "memory")

__device__ __forceinline__ void ldsm4(uint32_t* r, uint32_t addr) {
    asm volatile("ldmatrix.sync.aligned.m8n8.x4.shared.b16 {%0,%1,%2,%3}, [%4];"
                 : "=r"(r[0]), "=r"(r[1]), "=r"(r[2]), "=r"(r[3]) : "r"(addr));
}
__device__ __forceinline__ void mma_bf16(float* c, const uint32_t* a, uint32_t b0, uint32_t b1) {
    asm volatile("mma.sync.aligned.m16n8k16.row.col.f32.bf16.bf16.f32 "
                 "{%0,%1,%2,%3}, {%4,%5,%6,%7}, {%8,%9}, {%0,%1,%2,%3};"
                 : "+f"(c[0]), "+f"(c[1]), "+f"(c[2]), "+f"(c[3])
                 : "r"(a[0]), "r"(a[1]), "r"(a[2]), "r"(a[3]), "r"(b0), "r"(b1));
}
__device__ __forceinline__ float swishf(float a) { return a / (1.0f + __expf(-a)); }
__device__ __forceinline__ void bsplit(float v, __nv_bfloat16& h, __nv_bfloat16& l) {
    h = __float2bfloat16(v);
    l = __float2bfloat16(v - __bfloat162float(h));
}

// ---------------- routing kernels ----------------
__global__ void k_init() {
    int i = blockIdx.x * blockDim.x + threadIdx.x;
    if (i < NE) { g_cnt[i] = 0; g_cur[i] = 0; }
    if (i < RCAP) g_rowtok[i] = -1;
}

__global__ void k_gate(const float* __restrict__ x, const float* __restrict__ Wg) {
    __shared__ float sWgT[NE * DIM];
    for (int idx = threadIdx.x; idx < DIM * NE; idx += blockDim.x) {
        int d = idx >> 3, e = idx & 7;
        sWgT[e * DIM + d] = Wg[idx];
    }
    __syncthreads();
    int warp = threadIdx.x >> 5, lane = threadIdx.x & 31;
    int t = blockIdx.x * 8 + warp;
    const float* xr = x + (size_t)t * DIM;
    float acc[NE];
#pragma unroll
    for (int e = 0; e < NE; e++) acc[e] = 0.0f;
    for (int d = lane; d < DIM; d += 32) {
        float xv = xr[d];
#pragma unroll
        for (int e = 0; e < NE; e++) acc[e] += xv * sWgT[e * DIM + d];
    }
#pragma unroll
    for (int off = 16; off; off >>= 1)
#pragma unroll
        for (int e = 0; e < NE; e++) acc[e] += __shfl_xor_sync(0xffffffffu, acc[e], off);
    if (lane == 0) {
        int e0 = 0; float v0 = acc[0];
#pragma unroll
        for (int e = 1; e < NE; e++) if (acc[e] > v0) { v0 = acc[e]; e0 = e; }
        int e1 = -1; float v1 = -1e30f;
#pragma unroll
        for (int e = 0; e < NE; e++) if (e != e0 && acc[e] > v1) { v1 = acc[e]; e1 = e; }
        float ex = __expf(v1 - v0);
        g_tope[t * 2 + 0] = e0; g_topp[t * 2 + 0] = 1.0f / (1.0f + ex);
        g_tope[t * 2 + 1] = e1; g_topp[t * 2 + 1] = ex / (1.0f + ex);
        atomicAdd(&g_cnt[e0], 1);
        atomicAdd(&g_cnt[e1], 1);
    }
}

__global__ void k_offsets() {
    if (threadIdx.x == 0) {
        int o = 0;
#pragma unroll
        for (int e = 0; e < NE; e++) {
            g_off[e] = o;
            o += ((g_cnt[e] + 127) / 128) * 128;
        }
        g_off[NE] = o;
    }
}

__global__ void k_scatter() {
    int i = blockIdx.x * blockDim.x + threadIdx.x;
    if (i >= T_TOK * 2) return;
    int e = g_tope[i];
    int pos = g_off[e] + atomicAdd(&g_cur[e], 1);
    g_rowtok[pos] = i >> 1;
    g_roww[pos] = g_topp[i];
}

__global__ void k_gather(const float* __restrict__ x) {
    int r = blockIdx.x;
    int t = g_rowtok[r];
    int i = threadIdx.x;
    float4 v = make_float4(0.f, 0.f, 0.f, 0.f);
    if (t >= 0) v = ((const float4*)(x + (size_t)t * DIM))[i];
    __nv_bfloat16 h[4], l[4];
    bsplit(v.x, h[0], l[0]); bsplit(v.y, h[1], l[1]);
    bsplit(v.z, h[2], l[2]); bsplit(v.w, h[3], l[3]);
    size_t off = (size_t)r * DIM + i * 4;
    *(ushort4*)(g_Xh + off) = make_ushort4(*(unsigned short*)&h[0], *(unsigned short*)&h[1],
                                           *(unsigned short*)&h[2], *(unsigned short*)&h[3]);
    *(ushort4*)(g_Xl + off) = make_ushort4(*(unsigned short*)&l[0], *(unsigned short*)&l[1],
                                           *(unsigned short*)&l[2], *(unsigned short*)&l[3]);
}

// W1/W2 [e][d][h] -> Wc [e][2h+p][d] (bf16 h/l), interleaved columns
__global__ void k_tr12(const float* __restrict__ src, int p) {
    __shared__ float t[32][33];
    int e = blockIdx.z;
    const float* s = src + (size_t)e * DIM * HID;
    int h0 = blockIdx.x * 32, d0 = blockIdx.y * 32;
    int tx = threadIdx.x, ty = threadIdx.y;
#pragma unroll
    for (int i = ty; i < 32; i += 8)
        t[i][tx] = s[(size_t)(d0 + i) * HID + h0 + tx];
    __syncthreads();
#pragma unroll
    for (int i = ty; i < 32; i += 8) {
        float v = t[tx][i];
        int n = 2 * (h0 + i) + p;
        __nv_bfloat16 h, l; bsplit(v, h, l);
        size_t off = ((size_t)e * 2 * HID + n) * DIM + d0 + tx;
        g_Wch[off] = h; g_Wcl[off] = l;
    }
}

// W3 [e][h][d] -> W3T [e][d][h] (bf16 h/l)
__global__ void k_tr3(const float* __restrict__ src) {
    __shared__ float t[32][33];
    int e = blockIdx.z;
    const float* s = src + (size_t)e * HID * DIM;
    int d0 = blockIdx.x * 32, h0 = blockIdx.y * 32;
    int tx = threadIdx.x, ty = threadIdx.y;
#pragma unroll
    for (int i = ty; i < 32; i += 8)
        t[i][tx] = s[(size_t)(h0 + i) * DIM + d0 + tx];
    __syncthreads();
#pragma unroll
    for (int i = ty; i < 32; i += 8) {
        float v = t[tx][i];
        __nv_bfloat16 h, l; bsplit(v, h, l);
        size_t off = ((size_t)e * DIM + d0 + i) * HID + h0 + tx;
        g_W3h[off] = h; g_W3l[off] = l;
    }
}

// ---------------- stage loader: 128 threads, 16 cp16 each ----------------
__device__ __forceinline__ void load_stage(
    uint32_t st, int tid, int k0, int kstride,
    const __nv_bfloat16* Ah, const __nv_bfloat16* Al,
    const __nv_bfloat16* Bh, const __nv_bfloat16* Bl)
{
#pragma unroll
    for (int rep = 0; rep < 4; rep++) {
        int c = tid + rep * 128;          // 0..511
        int row = c >> 2, kc = c & 3;
        uint32_t doff = row * ROWB + kc * 16;
        size_t goff = (size_t)row * kstride + k0 + kc * 8;
        cp16(st + doff,             Ah + goff);
        cp16(st + TILEB + doff,     Al + goff);
        cp16(st + 2 * TILEB + doff, Bh + goff);
        cp16(st + 3 * TILEB + doff, Bl + goff);
    }
    CP_COMMIT();
}

// compute one BK=32 stage, warptile 64x64; B loaded in halves to cap live regs
__device__ __forceinline__ void compute_stage(
    uint32_t st, int warpM, int warpN, int lane, float acc[4][8][4])
{
    int mlane = lane & 7;
    int mid = lane >> 3;
#pragma unroll
    for (int ks = 0; ks < 2; ks++) {
        uint32_t ah[4][4], al[4][4];
#pragma unroll
        for (int mi = 0; mi < 4; mi++) {
            int row = warpM * 64 + mi * 16 + ((mid & 1) << 3) + mlane;
            int colB = ks * 32 + ((mid >> 1) << 4);
            ldsm4(ah[mi], st + row * ROWB + colB);
            ldsm4(al[mi], st + TILEB + row * ROWB + colB);
        }
#pragma unroll
        for (int njp = 0; njp < 2; njp++) {
            uint32_t bh[2][4], bl[2][4];
#pragma unroll
            for (int jj = 0; jj < 2; jj++) {
                int nj = njp * 2 + jj;
                int row = warpN * 64 + nj * 16 + ((mid >> 1) << 3) + mlane;
                int colB = ks * 32 + ((mid & 1) << 4);
                ldsm4(bh[jj], st + 2 * TILEB + row * ROWB + colB);
                ldsm4(bl[jj], st + 3 * TILEB + row * ROWB + colB);
            }
#pragma unroll
            for (int mi = 0; mi < 4; mi++)
#pragma unroll
                for (int jj = 0; jj < 2; jj++)
#pragma unroll
                    for (int tt = 0; tt < 2; tt++) {
                        int ni = (njp * 2 + jj) * 2 + tt;
                        mma_bf16(acc[mi][ni], ah[mi], bh[jj][tt * 2], bh[jj][tt * 2 + 1]);
                        mma_bf16(acc[mi][ni], ah[mi], bl[jj][tt * 2], bl[jj][tt * 2 + 1]);
                        mma_bf16(acc[mi][ni], al[mi], bh[jj][tt * 2], bh[jj][tt * 2 + 1]);
                    }
        }
    }
}

#define GEMM_MAINLOOP(NC, KSTRIDE)                                                  \
    load_stage(sb, tid, 0, KSTRIDE, Ah, Al, Bh, Bl);                                \
    load_stage(sb + STAGEB, tid, BK, KSTRIDE, Ah, Al, Bh, Bl);                      \
    for (int c = 0; c < (NC); c++) {                                                \
        if (c == (NC) - 1) { CP_WAIT0(); } else { CP_WAIT1(); }                     \
        __syncthreads();                                                            \
        compute_stage(sb + (c & 1) * STAGEB, warpM, warpN, lane, acc);              \
        __syncthreads();                                                            \
        if (c + 2 < (NC))                                                           \
            load_stage(sb + (c & 1) * STAGEB, tid, (c + 2) * BK, KSTRIDE,           \
                       Ah, Al, Bh, Bl);                                             \
    }

// ---------------- GEMM1: [RCAP,4096] = X @ Wc, epilogue SwiGLU -> Sh/Sl ----------------
__global__ __launch_bounds__(128, 2) void k_gemm1() {
    int row0 = blockIdx.y * BM;
    int e = 0;
#pragma unroll
    for (int i = 1; i < NE; i++) if (g_off[i] <= row0) e = i;
    if (g_cnt[e] - (row0 - g_off[e]) <= 0) return;

    extern __shared__ __align__(128) char smem[];
    uint32_t sb = smem_u32(smem);
    int tid = threadIdx.x, wid = tid >> 5, lane = tid & 31;
    int warpM = wid >> 1, warpN = wid & 1;
    int n0 = blockIdx.x * BN;

    const __nv_bfloat16* Ah = g_Xh + (size_t)row0 * DIM;
    const __nv_bfloat16* Al = g_Xl + (size_t)row0 * DIM;
    const __nv_bfloat16* Bh = g_Wch + (size_t)e * 2 * HID * DIM + (size_t)n0 * DIM;
    const __nv_bfloat16* Bl = g_Wcl + (size_t)e * 2 * HID * DIM + (size_t)n0 * DIM;

    float acc[4][8][4];
#pragma unroll
    for (int a = 0; a < 4; a++)
#pragma unroll
        for (int b = 0; b < 8; b++)
#pragma unroll
            for (int c = 0; c < 4; c++) acc[a][b][c] = 0.0f;

    GEMM_MAINLOOP(DIM / BK, DIM)

    // epilogue: (c0,c1)=(a1,a2)@row r, (c2,c3)=(a1,a2)@row r+8
    int qrow = lane >> 2, qcol = lane & 3;
#pragma unroll
    for (int mi = 0; mi < 4; mi++) {
        int r = row0 + warpM * 64 + mi * 16 + qrow;
#pragma unroll
        for (int ni = 0; ni < 8; ni++) {
            int n = n0 + warpN * 64 + ni * 8 + qcol * 2;   // even
            int jg = n >> 1;
            float v0 = swishf(acc[mi][ni][0]) * acc[mi][ni][1];
            float v1 = swishf(acc[mi][ni][2]) * acc[mi][ni][3];
            __nv_bfloat16 h, l;
            bsplit(v0, h, l);
            g_Sh[(size_t)r * HID + jg] = h;       g_Sl[(size_t)r * HID + jg] = l;
            bsplit(v1, h, l);
            g_Sh[(size_t)(r + 8) * HID + jg] = h; g_Sl[(size_t)(r + 8) * HID + jg] = l;
        }
    }
}

// ---------------- GEMM2: out[t] += w * (S @ W3T) ----------------
__global__ __launch_bounds__(128, 2) void k_gemm2(float* __restrict__ out) {
    int row0 = blockIdx.y * BM;
    int e = 0;
#pragma unroll
    for (int i = 1; i < NE; i++) if (g_off[i] <= row0) e = i;
    if (g_cnt[e] - (row0 - g_off[e]) <= 0) return;

    extern __shared__ __align__(128) char smem[];
    uint32_t sb = smem_u32(smem);
    int tid = threadIdx.x, wid = tid >> 5, lane = tid & 31;
    int warpM = wid >> 1, warpN = wid & 1;
    int n0 = blockIdx.x * BN;

    const __nv_bfloat16* Ah = g_Sh + (size_t)row0 * HID;
    const __nv_bfloat16* Al = g_Sl + (size_t)row0 * HID;
    const __nv_bfloat16* Bh = g_W3h + (size_t)e * DIM * HID + (size_t)n0 * HID;
    const __nv_bfloat16* Bl = g_W3l + (size_t)e * DIM * HID + (size_t)n0 * HID;

    float acc[4][8][4];
#pragma unroll
    for (int a = 0; a < 4; a++)
#pragma unroll
        for (int b = 0; b < 8; b++)
#pragma unroll
            for (int c = 0; c < 4; c++) acc[a][b][c] = 0.0f;

    GEMM_MAINLOOP(HID / BK, HID)

    int qrow = lane >> 2, qcol = lane & 3;
#pragma unroll
    for (int mi = 0; mi < 4; mi++) {
        int rbase = row0 + warpM * 64 + mi * 16 + qrow;
#pragma unroll
        for (int half = 0; half < 2; half++) {
            int r = rbase + half * 8;
            int t = g_rowtok[r];
            if (t < 0) continue;
            float wgt = g_roww[r];
            float* orow = out + (size_t)t * DIM;
#pragma unroll
            for (int ni = 0; ni < 8; ni++) {
                int colg = n0 + warpN * 64 + ni * 8 + qcol * 2;
                atomicAdd(orow + colg,     wgt * acc[mi][ni][half * 2]);
                atomicAdd(orow + colg + 1, wgt * acc[mi][ni][half * 2 + 1]);
            }
        }
    }
}

// ---------------- launch ----------------
extern "C" void kernel_launch(void* const* d_in, const int* in_sizes, int n_in,
                              void* d_out, int out_size) {
    const float* x  = (const float*)d_in[0];
    const float* Wg = (const float*)d_in[1];
    const float* W1 = (const float*)d_in[2];
    const float* W2 = (const float*)d_in[3];
    const float* W3 = (const float*)d_in[4];
    float* out = (float*)d_out;

    cudaFuncSetAttribute(k_gemm1, cudaFuncAttributeMaxDynamicSharedMemorySize, SMEMSZ);
    cudaFuncSetAttribute(k_gemm2, cudaFuncAttributeMaxDynamicSharedMemorySize, SMEMSZ);

    cudaMemsetAsync(out, 0, (size_t)T_TOK * DIM * sizeof(float));
    k_init<<<(RCAP + 255) / 256, 256>>>();
    k_gate<<<T_TOK / 8, 256>>>(x, Wg);
    k_offsets<<<1, 32>>>();
    k_scatter<<<(T_TOK * 2 + 255) / 256, 256>>>();
    k_gather<<<RCAP, 256>>>(x);
    k_tr12<<<dim3(HID / 32, DIM / 32, NE), dim3(32, 8)>>>(W1, 0);
    k_tr12<<<dim3(HID / 32, DIM / 32, NE), dim3(32, 8)>>>(W2, 1);
    k_tr3<<<dim3(DIM / 32, HID / 32, NE), dim3(32, 8)>>>(W3);

    k_gemm1<<<dim3(2 * HID / BN, RCAP / BM), 128, SMEMSZ>>>();
    k_gemm2<<<dim3(DIM / BN, RCAP / BM), 128, SMEMSZ>>>(out);
}

// round 7
// speedup vs baseline: 2.1103x; 1.0196x over previous
#include <cuda_runtime.h>
#include <cuda_bf16.h>
#include <cstdint>

#define T_TOK 8192
#define DIM   1024
#define HID   2048
#define NE    8
#define BM    128
#define BN    128
#define BK    32
#define RCAP  (T_TOK*2 + NE*128)   // 17408 rows = 136 tiles of 128

#define ROWB   80
#define TILEB  (128*ROWB)          // 10240 B
#define STAGEB (4*TILEB)           // Ah, Al, Bh, Bl = 40960 B
#define SMEMSZ (2*STAGEB)          // 81920 B -> 2 CTAs/SM

// ---------------- device scratch ----------------
__device__ int   g_cnt[NE], g_cur[NE], g_off[NE + 1];
__device__ int   g_tope[T_TOK * 2];
__device__ float g_topp[T_TOK * 2];
__device__ int   g_rowtok[RCAP];
__device__ float g_roww[RCAP];
__device__ __nv_bfloat16 g_Xh[(size_t)RCAP * DIM];
__device__ __nv_bfloat16 g_Xl[(size_t)RCAP * DIM];
__device__ __nv_bfloat16 g_Sh[(size_t)RCAP * HID];
__device__ __nv_bfloat16 g_Sl[(size_t)RCAP * HID];
__device__ __nv_bfloat16 g_Wch[(size_t)NE * 2 * HID * DIM];  // [e][2h+p][d]
__device__ __nv_bfloat16 g_Wcl[(size_t)NE * 2 * HID * DIM];
__device__ __nv_bfloat16 g_W3h[(size_t)NE * DIM * HID];      // [e][d][h]
__device__ __nv_bfloat16 g_W3l[(size_t)NE * DIM * HID];

// ---------------- helpers ----------------
__device__ __forceinline__ uint32_t smem_u32(const void* p) {
    uint32_t a;
    asm("{ .reg .u64 t; cvta.to.shared.u64 t, %1; cvt.u32.u64 %0, t; }" : "=r"(a) : "l"(p));
    return a;
}
__device__ __forceinline__ void cp16(uint32_t dst, const void* src) {
    asm volatile("cp.async.cg.shared.global [%0], [%1], 16;" :: "r"(dst), "l"(src));
}
#define CP_COMMIT() asm volatile("cp.async.commit_group;" ::: "memory")
#define CP_WAIT0()  asm volatile("cp.async.wait_group 0;" ::: "memory")

__device__ __forceinline__ void ldsm4(uint32_t* r, uint32_t addr) {
    asm volatile("ldmatrix.sync.aligned.m8n8.x4.shared.b16 {%0,%1,%2,%3}, [%4];"
                 : "=r"(r[0]), "=r"(r[1]), "=r"(r[2]), "=r"(r[3]) : "r"(addr));
}
__device__ __forceinline__ void mma_bf16(float* c, const uint32_t* a, uint32_t b0, uint32_t b1) {
    asm volatile("mma.sync.aligned.m16n8k16.row.col.f32.bf16.bf16.f32 "
                 "{%0,%1,%2,%3}, {%4,%5,%6,%7}, {%8,%9}, {%0,%1,%2,%3};"
                 : "+f"(c[0]), "+f"(c[1]), "+f"(c[2]), "+f"(c[3])
                 : "r"(a[0]), "r"(a[1]), "r"(a[2]), "r"(a[3]), "r"(b0), "r"(b1));
}
__device__ __forceinline__ void redg_v2(float* p, float a, float b) {
    asm volatile("red.global.add.v2.f32 [%0], {%1, %2};" :: "l"(p), "f"(a), "f"(b) : "memory");
}
__device__ __forceinline__ float swishf(float a) { return a / (1.0f + __expf(-a)); }
__device__ __forceinline__ void bsplit(float v, __nv_bfloat16& h, __nv_bfloat16& l) {
    h = __float2bfloat16(v);
    l = __float2bfloat16(v - __bfloat162float(h));
}

// ---------------- routing kernels ----------------
__global__ void k_init() {
    int i = blockIdx.x * blockDim.x + threadIdx.x;
    if (i < NE) { g_cnt[i] = 0; g_cur[i] = 0; }
    if (i < RCAP) g_rowtok[i] = -1;
}

__global__ void k_gate(const float* __restrict__ x, const float* __restrict__ Wg) {
    __shared__ float sWgT[NE * DIM];
    for (int idx = threadIdx.x; idx < DIM * NE; idx += blockDim.x) {
        int d = idx >> 3, e = idx & 7;
        sWgT[e * DIM + d] = Wg[idx];
    }
    __syncthreads();
    int warp = threadIdx.x >> 5, lane = threadIdx.x & 31;
    int t = blockIdx.x * 8 + warp;
    const float* xr = x + (size_t)t * DIM;
    float acc[NE];
#pragma unroll
    for (int e = 0; e < NE; e++) acc[e] = 0.0f;
    for (int d = lane; d < DIM; d += 32) {
        float xv = xr[d];
#pragma unroll
        for (int e = 0; e < NE; e++) acc[e] += xv * sWgT[e * DIM + d];
    }
#pragma unroll
    for (int off = 16; off; off >>= 1)
#pragma unroll
        for (int e = 0; e < NE; e++) acc[e] += __shfl_xor_sync(0xffffffffu, acc[e], off);
    if (lane == 0) {
        int e0 = 0; float v0 = acc[0];
#pragma unroll
        for (int e = 1; e < NE; e++) if (acc[e] > v0) { v0 = acc[e]; e0 = e; }
        int e1 = -1; float v1 = -1e30f;
#pragma unroll
        for (int e = 0; e < NE; e++) if (e != e0 && acc[e] > v1) { v1 = acc[e]; e1 = e; }
        float ex = __expf(v1 - v0);
        g_tope[t * 2 + 0] = e0; g_topp[t * 2 + 0] = 1.0f / (1.0f + ex);
        g_tope[t * 2 + 1] = e1; g_topp[t * 2 + 1] = ex / (1.0f + ex);
        atomicAdd(&g_cnt[e0], 1);
        atomicAdd(&g_cnt[e1], 1);
    }
}

__global__ void k_offsets() {
    if (threadIdx.x == 0) {
        int o = 0;
#pragma unroll
        for (int e = 0; e < NE; e++) {
            g_off[e] = o;
            o += ((g_cnt[e] + 127) / 128) * 128;
        }
        g_off[NE] = o;
    }
}

__global__ void k_scatter() {
    int i = blockIdx.x * blockDim.x + threadIdx.x;
    if (i >= T_TOK * 2) return;
    int e = g_tope[i];
    int pos = g_off[e] + atomicAdd(&g_cur[e], 1);
    g_rowtok[pos] = i >> 1;
    g_roww[pos] = g_topp[i];
}

__global__ void k_gather(const float* __restrict__ x) {
    int r = blockIdx.x;
    int t = g_rowtok[r];
    int i = threadIdx.x;
    float4 v = make_float4(0.f, 0.f, 0.f, 0.f);
    if (t >= 0) v = ((const float4*)(x + (size_t)t * DIM))[i];
    __nv_bfloat16 h[4], l[4];
    bsplit(v.x, h[0], l[0]); bsplit(v.y, h[1], l[1]);
    bsplit(v.z, h[2], l[2]); bsplit(v.w, h[3], l[3]);
    size_t off = (size_t)r * DIM + i * 4;
    *(ushort4*)(g_Xh + off) = make_ushort4(*(unsigned short*)&h[0], *(unsigned short*)&h[1],
                                           *(unsigned short*)&h[2], *(unsigned short*)&h[3]);
    *(ushort4*)(g_Xl + off) = make_ushort4(*(unsigned short*)&l[0], *(unsigned short*)&l[1],
                                           *(unsigned short*)&l[2], *(unsigned short*)&l[3]);
}

// W1/W2 [e][d][h] -> Wc [e][2h+p][d] (bf16 h/l), interleaved columns
__global__ void k_tr12(const float* __restrict__ src, int p) {
    __shared__ float t[32][33];
    int e = blockIdx.z;
    const float* s = src + (size_t)e * DIM * HID;
    int h0 = blockIdx.x * 32, d0 = blockIdx.y * 32;
    int tx = threadIdx.x, ty = threadIdx.y;
#pragma unroll
    for (int i = ty; i < 32; i += 8)
        t[i][tx] = s[(size_t)(d0 + i) * HID + h0 + tx];
    __syncthreads();
#pragma unroll
    for (int i = ty; i < 32; i += 8) {
        float v = t[tx][i];
        int n = 2 * (h0 + i) + p;
        __nv_bfloat16 h, l; bsplit(v, h, l);
        size_t off = ((size_t)e * 2 * HID + n) * DIM + d0 + tx;
        g_Wch[off] = h; g_Wcl[off] = l;
    }
}

// W3 [e][h][d] -> W3T [e][d][h] (bf16 h/l)
__global__ void k_tr3(const float* __restrict__ src) {
    __shared__ float t[32][33];
    int e = blockIdx.z;
    const float* s = src + (size_t)e * HID * DIM;
    int d0 = blockIdx.x * 32, h0 = blockIdx.y * 32;
    int tx = threadIdx.x, ty = threadIdx.y;
#pragma unroll
    for (int i = ty; i < 32; i += 8)
        t[i][tx] = s[(size_t)(h0 + i) * DIM + d0 + tx];
    __syncthreads();
#pragma unroll
    for (int i = ty; i < 32; i += 8) {
        float v = t[tx][i];
        __nv_bfloat16 h, l; bsplit(v, h, l);
        size_t off = ((size_t)e * DIM + d0 + i) * HID + h0 + tx;
        g_W3h[off] = h; g_W3l[off] = l;
    }
}

// ---------------- stage loader: 128 threads, 16 cp16 each ----------------
__device__ __forceinline__ void load_stage(
    uint32_t st, int tid, int k0, int kstride,
    const __nv_bfloat16* Ah, const __nv_bfloat16* Al,
    const __nv_bfloat16* Bh, const __nv_bfloat16* Bl)
{
#pragma unroll
    for (int rep = 0; rep < 4; rep++) {
        int c = tid + rep * 128;
        int row = c >> 2, kc = c & 3;
        uint32_t doff = row * ROWB + kc * 16;
        size_t goff = (size_t)row * kstride + k0 + kc * 8;
        cp16(st + doff,             Ah + goff);
        cp16(st + TILEB + doff,     Al + goff);
        cp16(st + 2 * TILEB + doff, Bh + goff);
        cp16(st + 3 * TILEB + doff, Bl + goff);
    }
    CP_COMMIT();
}

// compute one BK=32 stage, warptile 64x64
__device__ __forceinline__ void compute_stage(
    uint32_t st, int warpM, int warpN, int lane, float acc[4][8][4])
{
    int mlane = lane & 7;
    int mid = lane >> 3;
#pragma unroll
    for (int ks = 0; ks < 2; ks++) {
        uint32_t ah[4][4], al[4][4];
#pragma unroll
        for (int mi = 0; mi < 4; mi++) {
            int row = warpM * 64 + mi * 16 + ((mid & 1) << 3) + mlane;
            int colB = ks * 32 + ((mid >> 1) << 4);
            ldsm4(ah[mi], st + row * ROWB + colB);
            ldsm4(al[mi], st + TILEB + row * ROWB + colB);
        }
#pragma unroll
        for (int njp = 0; njp < 2; njp++) {
            uint32_t bh[2][4], bl[2][4];
#pragma unroll
            for (int jj = 0; jj < 2; jj++) {
                int nj = njp * 2 + jj;
                int row = warpN * 64 + nj * 16 + ((mid >> 1) << 3) + mlane;
                int colB = ks * 32 + ((mid & 1) << 4);
                ldsm4(bh[jj], st + 2 * TILEB + row * ROWB + colB);
                ldsm4(bl[jj], st + 3 * TILEB + row * ROWB + colB);
            }
#pragma unroll
            for (int mi = 0; mi < 4; mi++)
#pragma unroll
                for (int jj = 0; jj < 2; jj++)
#pragma unroll
                    for (int tt = 0; tt < 2; tt++) {
                        int ni = (njp * 2 + jj) * 2 + tt;
                        mma_bf16(acc[mi][ni], ah[mi], bh[jj][tt * 2], bh[jj][tt * 2 + 1]);
                        mma_bf16(acc[mi][ni], ah[mi], bl[jj][tt * 2], bl[jj][tt * 2 + 1]);
                        mma_bf16(acc[mi][ni], al[mi], bh[jj][tt * 2], bh[jj][tt * 2 + 1]);
                    }
        }
    }
}

// single-sync multistage loop (N=2): wait -> sync -> issue next load -> compute
#define GEMM_MAINLOOP(NC, KSTRIDE)                                                  \
    load_stage(sb, tid, 0, KSTRIDE, Ah, Al, Bh, Bl);                                \
    for (int c = 0; c < (NC); c++) {                                                \
        CP_WAIT0();                                                                 \
        __syncthreads();                                                            \
        if (c + 1 < (NC))                                                           \
            load_stage(sb + ((c + 1) & 1) * STAGEB, tid, (c + 1) * BK, KSTRIDE,     \
                       Ah, Al, Bh, Bl);                                             \
        compute_stage(sb + (c & 1) * STAGEB, warpM, warpN, lane, acc);              \
    }

// ---------------- GEMM1: [RCAP,4096] = X @ Wc, epilogue SwiGLU -> Sh/Sl ----------------
__global__ __launch_bounds__(128, 2) void k_gemm1() {
    int row0 = blockIdx.y * BM;
    int e = 0;
#pragma unroll
    for (int i = 1; i < NE; i++) if (g_off[i] <= row0) e = i;
    if (g_cnt[e] - (row0 - g_off[e]) <= 0) return;

    extern __shared__ __align__(128) char smem[];
    uint32_t sb = smem_u32(smem);
    int tid = threadIdx.x, wid = tid >> 5, lane = tid & 31;
    int warpM = wid >> 1, warpN = wid & 1;
    int n0 = blockIdx.x * BN;

    const __nv_bfloat16* Ah = g_Xh + (size_t)row0 * DIM;
    const __nv_bfloat16* Al = g_Xl + (size_t)row0 * DIM;
    const __nv_bfloat16* Bh = g_Wch + (size_t)e * 2 * HID * DIM + (size_t)n0 * DIM;
    const __nv_bfloat16* Bl = g_Wcl + (size_t)e * 2 * HID * DIM + (size_t)n0 * DIM;

    float acc[4][8][4];
#pragma unroll
    for (int a = 0; a < 4; a++)
#pragma unroll
        for (int b = 0; b < 8; b++)
#pragma unroll
            for (int c = 0; c < 4; c++) acc[a][b][c] = 0.0f;

    GEMM_MAINLOOP(DIM / BK, DIM)

    // epilogue: SwiGLU, stage bf16 h/l through smem, coalesced 16B stores
    __syncthreads();                      // all warps done reading stage buffers
    char* stg = smem + wid * 4096;        // per-warp region: h @0 (1280B), l @2048
    int qrow = lane >> 2, qcol = lane & 3;
    int jgb = (n0 >> 1) + warpN * 32;
#pragma unroll
    for (int mi = 0; mi < 4; mi++) {
        int r0 = row0 + warpM * 64 + mi * 16;
#pragma unroll
        for (int ni = 0; ni < 8; ni++) {
            int col = ni * 4 + qcol;
            float v0 = swishf(acc[mi][ni][0]) * acc[mi][ni][1];
            float v1 = swishf(acc[mi][ni][2]) * acc[mi][ni][3];
            __nv_bfloat16 h, l;
            bsplit(v0, h, l);
            *(__nv_bfloat16*)(stg + qrow * 80 + col * 2) = h;
            *(__nv_bfloat16*)(stg + 2048 + qrow * 80 + col * 2) = l;
            bsplit(v1, h, l);
            *(__nv_bfloat16*)(stg + (qrow + 8) * 80 + col * 2) = h;
            *(__nv_bfloat16*)(stg + 2048 + (qrow + 8) * 80 + col * 2) = l;
        }
        __syncwarp();
#pragma unroll
        for (int k = 0; k < 2; k++) {
            int chunk = lane + 32 * k;            // 0..63 = 16 rows x 4 parts
            int row = chunk >> 2, part = chunk & 3;
            uint4 vh = *(uint4*)(stg + row * 80 + part * 16);
            uint4 vl = *(uint4*)(stg + 2048 + row * 80 + part * 16);
            size_t o = (size_t)(r0 + row) * HID + jgb + part * 8;
            *(uint4*)(g_Sh + o) = vh;
            *(uint4*)(g_Sl + o) = vl;
        }
        __syncwarp();
    }
}

// ---------------- GEMM2: out[t] += w * (S @ W3T) ----------------
__global__ __launch_bounds__(128, 2) void k_gemm2(float* __restrict__ out) {
    int row0 = blockIdx.y * BM;
    int e = 0;
#pragma unroll
    for (int i = 1; i < NE; i++) if (g_off[i] <= row0) e = i;
    if (g_cnt[e] - (row0 - g_off[e]) <= 0) return;

    extern __shared__ __align__(128) char smem[];
    uint32_t sb = smem_u32(smem);
    int tid = threadIdx.x, wid = tid >> 5, lane = tid & 31;
    int warpM = wid >> 1, warpN = wid & 1;
    int n0 = blockIdx.x * BN;

    const __nv_bfloat16* Ah = g_Sh + (size_t)row0 * HID;
    const __nv_bfloat16* Al = g_Sl + (size_t)row0 * HID;
    const __nv_bfloat16* Bh = g_W3h + (size_t)e * DIM * HID + (size_t)n0 * HID;
    const __nv_bfloat16* Bl = g_W3l + (size_t)e * DIM * HID + (size_t)n0 * HID;

    float acc[4][8][4];
#pragma unroll
    for (int a = 0; a < 4; a++)
#pragma unroll
        for (int b = 0; b < 8; b++)
#pragma unroll
            for (int c = 0; c < 4; c++) acc[a][b][c] = 0.0f;

    GEMM_MAINLOOP(HID / BK, HID)

    int qrow = lane >> 2, qcol = lane & 3;
#pragma unroll
    for (int mi = 0; mi < 4; mi++) {
        int rbase = row0 + warpM * 64 + mi * 16 + qrow;
#pragma unroll
        for (int half = 0; half < 2; half++) {
            int r = rbase + half * 8;
            int t = g_rowtok[r];
            if (t < 0) continue;
            float wgt = g_roww[r];
            float* orow = out + (size_t)t * DIM;
#pragma unroll
            for (int ni = 0; ni < 8; ni++) {
                int colg = n0 + warpN * 64 + ni * 8 + qcol * 2;
                redg_v2(orow + colg, wgt * acc[mi][ni][half * 2],
                                     wgt * acc[mi][ni][half * 2 + 1]);
            }
        }
    }
}

// ---------------- launch ----------------
extern "C" void kernel_launch(void* const* d_in, const int* in_sizes, int n_in,
                              void* d_out, int out_size) {
    const float* x  = (const float*)d_in[0];
    const float* Wg = (const float*)d_in[1];
    const float* W1 = (const float*)d_in[2];
    const float* W2 = (const float*)d_in[3];
    const float* W3 = (const float*)d_in[4];
    float* out = (float*)d_out;

    cudaFuncSetAttribute(k_gemm1, cudaFuncAttributeMaxDynamicSharedMemorySize, SMEMSZ);
    cudaFuncSetAttribute(k_gemm2, cudaFuncAttributeMaxDynamicSharedMemorySize, SMEMSZ);

    cudaMemsetAsync(out, 0, (size_t)T_TOK * DIM * sizeof(float));
    k_init<<<(RCAP + 255) / 256, 256>>>();
    k_gate<<<T_TOK / 8, 256>>>(x, Wg);
    k_offsets<<<1, 32>>>();
    k_scatter<<<(T_TOK * 2 + 255) / 256, 256>>>();
    k_gather<<<RCAP, 256>>>(x);
    k_tr12<<<dim3(HID / 32, DIM / 32, NE), dim3(32, 8)>>>(W1, 0);
    k_tr12<<<dim3(HID / 32, DIM / 32, NE), dim3(32, 8)>>>(W2, 1);
    k_tr3<<<dim3(DIM / 32, HID / 32, NE), dim3(32, 8)>>>(W3);

    k_gemm1<<<dim3(2 * HID / BN, RCAP / BM), 128, SMEMSZ>>>();
    k_gemm2<<<dim3(DIM / BN, RCAP / BM), 128, SMEMSZ>>>(out);
}